// round 16
// baseline (speedup 1.0000x reference)
#include <cuda_runtime.h>
#include <cuda_fp16.h>
#include <math.h>
#include <stdint.h>

#define SQ   2048
#define EE   2048
#define HH   16
#define QLR  1536
#define KLR  512
#define DNN  128
#define DRR  64
#define DVV  128
#define DQQ  192
#define N1C  2176

// -------- scratch --------
__device__ float g_c1  [SQ * N1C];
__device__ float g_q   [SQ * HH * DQQ];

__device__ __half g_Ah [SQ * EE];
__device__ __half g_Al [SQ * EE];
__device__ __half g_B1 [QLR * 3072];
__device__ __half g_B3 [QLR * 3072];
__device__ __half g_B2 [KLR * HH * 256];
__device__ __half g_BO [HH * DVV * EE];
__device__ __half g_A2h[SQ * KLR];
__device__ __half g_A2l[SQ * KLR];
__device__ __half g_kv [SQ * HH * 256];
__device__ __half g_kpe[SQ * DRR];

// ======================= helpers =======================
__device__ __forceinline__ uint32_t s2u(const void* p) {
    return (uint32_t)__cvta_generic_to_shared(p);
}
__device__ __forceinline__ void cpa(uint32_t d, const void* s) {
    asm volatile("cp.async.cg.shared.global [%0], [%1], 16;\n" :: "r"(d), "l"(s));
}
#define CP_COMMIT asm volatile("cp.async.commit_group;\n")
#define CP_WAIT0  asm volatile("cp.async.wait_group 0;\n")
#define CP_WAIT1  asm volatile("cp.async.wait_group 1;\n")
#define CP_WAIT2  asm volatile("cp.async.wait_group 2;\n")

__device__ __forceinline__ void ldsm4(uint32_t a, unsigned* d) {
    asm volatile("ldmatrix.sync.aligned.m8n8.x4.shared.b16 {%0,%1,%2,%3}, [%4];\n"
        : "=r"(d[0]), "=r"(d[1]), "=r"(d[2]), "=r"(d[3]) : "r"(a));
}
__device__ __forceinline__ void ldsm4t(uint32_t a, unsigned* d) {
    asm volatile("ldmatrix.sync.aligned.m8n8.x4.trans.shared.b16 {%0,%1,%2,%3}, [%4];\n"
        : "=r"(d[0]), "=r"(d[1]), "=r"(d[2]), "=r"(d[3]) : "r"(a));
}
__device__ __forceinline__ void mma_f16(float* d, const unsigned* a, const unsigned* b) {
    asm volatile(
        "mma.sync.aligned.m16n8k16.row.col.f32.f16.f16.f32 "
        "{%0,%1,%2,%3}, {%4,%5,%6,%7}, {%8,%9}, {%0,%1,%2,%3};\n"
        : "+f"(d[0]), "+f"(d[1]), "+f"(d[2]), "+f"(d[3])
        : "r"(a[0]), "r"(a[1]), "r"(a[2]), "r"(a[3]), "r"(b[0]), "r"(b[1]));
}
__device__ __forceinline__ unsigned short hfu(__half v) {
    return *(unsigned short*)&v;
}
__device__ __forceinline__ void packsplit(float x, float y, unsigned& h, unsigned& l) {
    __half xh = __float2half(x), yh = __float2half(y);
    __half xl = __float2half(x - __half2float(xh));
    __half yl = __float2half(y - __half2float(yh));
    h = (unsigned)hfu(xh) | ((unsigned)hfu(yh) << 16);
    l = (unsigned)hfu(xl) | ((unsigned)hfu(yl) << 16);
}
__device__ __forceinline__ unsigned packh2(float x, float y) {
    __half xh = __float2half(x), yh = __float2half(y);
    return (unsigned)hfu(xh) | ((unsigned)hfu(yh) << 16);
}
__device__ __forceinline__ void split8(const float* f, uint4& hv, uint4& lv) {
    unsigned hw[4], lw[4];
#pragma unroll
    for (int j = 0; j < 4; j++) packsplit(f[2 * j], f[2 * j + 1], hw[j], lw[j]);
    hv = make_uint4(hw[0], hw[1], hw[2], hw[3]);
    lv = make_uint4(lw[0], lw[1], lw[2], lw[3]);
}

// ======================= conversions ===========================
__global__ void conv_split(const float* __restrict__ in,
                           __half* __restrict__ hi,
                           __half* __restrict__ lo, int n) {
    int i = (blockIdx.x * blockDim.x + threadIdx.x) * 8;
    if (i >= n) return;
    float f[8];
    *(float4*)&f[0] = *(const float4*)(in + i);
    *(float4*)&f[4] = *(const float4*)(in + i + 4);
    uint4 hv, lv;
    split8(f, hv, lv);
    *(uint4*)(hi + i) = hv;
    *(uint4*)(lo + i) = lv;
}
__global__ void conv_single(const float* __restrict__ in,
                            __half* __restrict__ o, int n) {
    int i = (blockIdx.x * blockDim.x + threadIdx.x) * 8;
    if (i >= n) return;
    float f[8];
    *(float4*)&f[0] = *(const float4*)(in + i);
    *(float4*)&f[4] = *(const float4*)(in + i + 4);
    unsigned w[4];
#pragma unroll
    for (int j = 0; j < 4; j++) w[j] = packh2(f[2 * j], f[2 * j + 1]);
    *(uint4*)(o + i) = make_uint4(w[0], w[1], w[2], w[3]);
}
__global__ void conv_singleN(const float* __restrict__ in,
                             __half* __restrict__ o,
                             int Nin, int colOff, int Nstr, int n) {
    int i = (blockIdx.x * blockDim.x + threadIdx.x) * 8;
    if (i >= n) return;
    int r = i / Nin, c = i % Nin;
    float f[8];
    *(float4*)&f[0] = *(const float4*)(in + i);
    *(float4*)&f[4] = *(const float4*)(in + i + 4);
    unsigned w[4];
#pragma unroll
    for (int j = 0; j < 4; j++) w[j] = packh2(f[2 * j], f[2 * j + 1]);
    *(uint4*)(o + (size_t)r * Nstr + colOff + c) = make_uint4(w[0], w[1], w[2], w[3]);
}

// ======================= merged RMSNorm (qa + ckv) ==========================
__global__ void rmsnorm2(const float* __restrict__ c1,
                         const float* __restrict__ wq,
                         const float* __restrict__ wk,
                         __half* __restrict__ qh, __half* __restrict__ ql,
                         __half* __restrict__ kh, __half* __restrict__ kl) {
    const int row = blockIdx.x;
    const int which = blockIdx.y;
    const int D = which ? KLR : QLR;
    const float* x = c1 + (size_t)row * N1C + (which ? QLR : 0);
    const float* w = which ? wk : wq;
    __half* hi = which ? kh : qh;
    __half* lo = which ? kl : ql;

    float ss = 0.f;
    for (int i = threadIdx.x; i < D; i += blockDim.x) { float v = x[i]; ss += v * v; }
#pragma unroll
    for (int m = 16; m; m >>= 1) ss += __shfl_xor_sync(0xffffffffu, ss, m);
    __shared__ float wsum[8];
    if ((threadIdx.x & 31) == 0) wsum[threadIdx.x >> 5] = ss;
    __syncthreads();
    float tot = 0.f;
#pragma unroll
    for (int i = 0; i < 8; i++) tot += wsum[i];
    float scale = rsqrtf(tot / (float)D + 1e-6f);
    for (int i = threadIdx.x; i < D; i += blockDim.x) {
        float v = x[i] * scale * w[i];
        __half h = __float2half(v);
        hi[(size_t)row * D + i] = h;
        lo[(size_t)row * D + i] = __float2half(v - __half2float(h));
    }
}

// ======================= bgemm2: fp16 A-x2 / B-x1 ===========================
#define BG_STAGE 24576
#define BG_SMEM  (3 * BG_STAGE)

__global__ __launch_bounds__(256, 2) void bgemm2(const __half* __restrict__ Ahg,
                                                 const __half* __restrict__ Alg,
                                                 const __half* __restrict__ Bg,
                                                 float* __restrict__ C,
                                                 __half* __restrict__ Ch,
                                                 int N, int K, int mode) {
    extern __shared__ char smem[];
    const uint32_t sb = s2u(smem);
    const int tid = threadIdx.x;
    const int lane = tid & 31, warp = tid >> 5;
    const int wm = warp >> 2, wn = warp & 3;
    const int g = lane >> 2, t = lane & 3;
    const int bm = blockIdx.y * 128, bn = blockIdx.x * 128;

    float acc[4][4][4];
#pragma unroll
    for (int mt = 0; mt < 4; mt++)
#pragma unroll
        for (int nt = 0; nt < 4; nt++)
#pragma unroll
            for (int k = 0; k < 4; k++) acc[mt][nt][k] = 0.f;

    const int nsteps = K >> 5;

    auto load_stage = [&](int s) {
        uint32_t base = sb + (s % 3) * BG_STAGE;
        int k0 = s << 5;
#pragma unroll
        for (int p = 0; p < 2; p++) {
            int id = tid + p * 256;
            int r = id >> 2, sg = id & 3;
            uint32_t dst = base + r * 64 + (((sg ^ ((r >> 1) & 3))) << 4);
            size_t go = (size_t)(bm + r) * K + k0 + sg * 8;
            cpa(dst, Ahg + go);
            cpa(dst + 8192, Alg + go);
        }
#pragma unroll
        for (int p = 0; p < 2; p++) {
            int id = tid + p * 256;
            int r = id >> 4, sg = id & 15;
            uint32_t dst = base + 16384 + r * 256 + ((sg ^ (r & 7)) << 4);
            size_t go = (size_t)(k0 + r) * N + bn + sg * 8;
            cpa(dst, Bg + go);
        }
        CP_COMMIT;
    };

    load_stage(0);
    if (nsteps > 1) load_stage(1);

    for (int s = 0; s < nsteps; s++) {
        if (s + 1 < nsteps) { CP_WAIT1; } else { CP_WAIT0; }
        __syncthreads();
        if (s + 2 < nsteps) load_stage(s + 2);

        uint32_t ab = sb + (s % 3) * BG_STAGE;
        uint32_t bb = ab + 16384;
        const int lr = (lane & 7) + 8 * ((lane >> 3) & 1);

#pragma unroll
        for (int kk = 0; kk < 32; kk += 16) {
            unsigned ah[4][4], al[4][4], bf[4][2];
            int sgA = (kk >> 3) + (lane >> 4);
#pragma unroll
            for (int mt = 0; mt < 4; mt++) {
                int row = wm * 64 + mt * 16 + lr;
                uint32_t a = ab + row * 64 + ((sgA ^ ((row >> 1) & 3)) << 4);
                ldsm4(a, ah[mt]);
                ldsm4(a + 8192, al[mt]);
            }
            int rB = kk + lr;
#pragma unroll
            for (int ntp = 0; ntp < 2; ntp++) {
                int sgB = wn * 4 + 2 * ntp + (lane >> 4);
                uint32_t b = bb + rB * 256 + ((sgB ^ (rB & 7)) << 4);
                unsigned t4[4];
                ldsm4t(b, t4);
                bf[2 * ntp][0] = t4[0]; bf[2 * ntp][1] = t4[1];
                bf[2 * ntp + 1][0] = t4[2]; bf[2 * ntp + 1][1] = t4[3];
            }
#pragma unroll
            for (int mt = 0; mt < 4; mt++)
#pragma unroll
                for (int nt = 0; nt < 4; nt++) {
                    mma_f16(acc[mt][nt], ah[mt], bf[nt]);
                    mma_f16(acc[mt][nt], al[mt], bf[nt]);
                }
        }
    }

    if (mode == 0) {
#pragma unroll
        for (int mt = 0; mt < 4; mt++) {
            int row = bm + wm * 64 + mt * 16 + g;
#pragma unroll
            for (int nt = 0; nt < 4; nt++) {
                int col = bn + wn * 32 + nt * 8 + 2 * t;
                if (col < N) {
                    *(float2*)&C[(size_t)row * N + col] =
                        make_float2(acc[mt][nt][0], acc[mt][nt][1]);
                    *(float2*)&C[(size_t)(row + 8) * N + col] =
                        make_float2(acc[mt][nt][2], acc[mt][nt][3]);
                }
            }
        }
    } else {
#pragma unroll
        for (int mt = 0; mt < 4; mt++) {
            int row = bm + wm * 64 + mt * 16 + g;
#pragma unroll
            for (int nt = 0; nt < 4; nt++) {
                int col = bn + wn * 32 + nt * 8 + 2 * t;
                *(unsigned*)(Ch + (size_t)row * N + col) =
                    packh2(acc[mt][nt][0], acc[mt][nt][1]);
                *(unsigned*)(Ch + (size_t)(row + 8) * N + col) =
                    packh2(acc[mt][nt][2], acc[mt][nt][3]);
            }
        }
    }
}

// ======================= RoPE-K =============================================
#define LOG2_10000_OVER_32 0.4152410118609203f

__global__ void rope_k_split(const float* __restrict__ src, int stride,
                             __half* __restrict__ kpe) {
    int w = (blockIdx.x * blockDim.x + threadIdx.x) >> 5;
    int lane = threadIdx.x & 31;
    if (w >= SQ) return;
    const float* base = src + (size_t)w * stride;
    float x0 = base[2 * lane];
    float x1 = base[2 * lane + 1];
    float invf = exp2f(-(float)lane * LOG2_10000_OVER_32);
    float ang = (float)w * invf;
    float sn, cs;
    sincosf(ang, &sn, &cs);
    kpe[(size_t)w * DRR + lane]      = __float2half(x0 * cs - x1 * sn);
    kpe[(size_t)w * DRR + 32 + lane] = __float2half(x1 * cs + x0 * sn);
}

// ======================= flash2: BM=64, occ 2, K/V split prefetch ===========
// smem: Qh 0..24K, Ql 24K..48K, K 48K..72K, V 72K..88K.
#define OQH 0
#define OQL 24576
#define OKO 49152
#define OVO 73728
#define FL2_SMEM 90112

__global__ __launch_bounds__(128) void flash2(const float* __restrict__ q,
                                              const __half* __restrict__ kv,
                                              const __half* __restrict__ kpe,
                                              __half* __restrict__ Oh,
                                              __half* __restrict__ Ol) {
    extern __shared__ char smem[];
    const uint32_t sb = s2u(smem);
    const int tid = threadIdx.x, lane = tid & 31, warp = tid >> 5;
    const int g = lane >> 2, t = lane & 3;
    const int h = blockIdx.y;
    const int qb = gridDim.x - 1 - blockIdx.x;
    const int q0 = qb * 64;
    const int r0 = warp * 16;
    const float scale = 0.07216878364870322f;

    auto load_K = [&](int k0) {
        for (int i = tid; i < 64 * 24; i += 128) {
            int r = i / 24, sg = i % 24;
            uint32_t off = r * 384 + ((sg ^ (r & 7)) << 4);
            if (sg < 16) {
                cpa(sb + OKO + off, kv + (size_t)(k0 + r) * (HH * 256) + h * 256 + sg * 8);
            } else {
                cpa(sb + OKO + off, kpe + (size_t)(k0 + r) * DRR + (sg - 16) * 8);
            }
        }
        CP_COMMIT;
    };
    auto load_V = [&](int k0) {
        for (int i = tid; i < 64 * 16; i += 128) {
            int r = i / 16, sg = i % 16;
            uint32_t off = r * 256 + ((sg ^ (r & 7)) << 4);
            cpa(sb + OVO + off, kv + (size_t)(k0 + r) * (HH * 256) + h * 256 + DNN + sg * 8);
        }
        CP_COMMIT;
    };

    // prologue: issue K0 then V0 (separate groups), then Q work
    load_K(0);
    load_V(0);

    // ---- Q load with fused RoPE + hi/lo split ----
    for (int i = tid; i < 64 * 24; i += 128) {
        int r = i / 24, sg = i % 24;
        int qrow = q0 + r;
        const float* qr = q + (size_t)qrow * (HH * DQQ) + h * DQQ;
        float f[8];
        if (sg < 16) {
            *(float4*)&f[0] = *(const float4*)(qr + sg * 8);
            *(float4*)&f[4] = *(const float4*)(qr + sg * 8 + 4);
        } else {
            int u_base = (sg - 16) * 8;
            int j_base = u_base & 31;
            float f2[16];
            const float* pe = qr + DNN + 2 * j_base;
#pragma unroll
            for (int v = 0; v < 4; v++) *(float4*)&f2[4 * v] = *(const float4*)(pe + 4 * v);
#pragma unroll
            for (int j2 = 0; j2 < 8; j2++) {
                int j = j_base + j2;
                float x0 = f2[2 * j2], x1 = f2[2 * j2 + 1];
                float invf = exp2f(-(float)j * LOG2_10000_OVER_32);
                float sn, cs;
                sincosf((float)qrow * invf, &sn, &cs);
                f[j2] = (u_base < 32) ? (x0 * cs - x1 * sn) : (x1 * cs + x0 * sn);
            }
        }
        uint4 hv, lv;
        split8(f, hv, lv);
        uint32_t off = r * 384 + ((sg ^ (r & 7)) << 4);
        *(uint4*)(smem + OQH + off) = hv;
        *(uint4*)(smem + OQL + off) = lv;
    }

    float m0 = -1e30f, m1 = -1e30f, l0 = 0.f, l1 = 0.f;
    float oacc[16][4];
#pragma unroll
    for (int nv = 0; nv < 16; nv++)
#pragma unroll
        for (int k = 0; k < 4; k++) oacc[nv][k] = 0.f;

    const int nkb = qb + 1;
    for (int kb = 0; kb < nkb; kb++) {
        const int k0 = kb * 64;
        const bool pre = (kb + 1 < nkb);
        // entering: outstanding groups {K(cur), V(cur)} (K committed first)
        CP_WAIT1;          // K(cur) landed for this thread
        __syncthreads();   // K visible to all (also Q stores on iter 0)

        // S = Q @ K^T
        float sacc[8][4];
#pragma unroll
        for (int nt = 0; nt < 8; nt++)
#pragma unroll
            for (int k = 0; k < 4; k++) sacc[nt][k] = 0.f;

        const int lr = (lane & 7) + 8 * ((lane >> 3) & 1);
#pragma unroll
        for (int kk = 0; kk < 192; kk += 16) {
            unsigned ah[4], al[4];
            int rowA = r0 + lr;
            int sgA = (kk >> 3) + (lane >> 4);
            uint32_t a = sb + OQH + rowA * 384 + ((sgA ^ (rowA & 7)) << 4);
            ldsm4(a, ah);
            ldsm4(a + (OQL - OQH), al);
            int sgB = (kk >> 3) + ((lane >> 3) & 1);
#pragma unroll
            for (int ntp = 0; ntp < 4; ntp++) {
                int rB = (2 * ntp + (lane >> 4)) * 8 + (lane & 7);
                uint32_t b = sb + OKO + rB * 384 + ((sgB ^ (rB & 7)) << 4);
                unsigned b4[4];
                ldsm4(b, b4);
                mma_f16(sacc[2 * ntp],     ah, &b4[0]);
                mma_f16(sacc[2 * ntp],     al, &b4[0]);
                mma_f16(sacc[2 * ntp + 1], ah, &b4[2]);
                mma_f16(sacc[2 * ntp + 1], al, &b4[2]);
            }
        }

        __syncthreads();               // all warps done reading K(cur)
        if (pre) load_K(k0 + 64);      // overlaps softmax + PV

        // mask + online softmax
        const int qi0 = q0 + r0 + g;
        const int qi1 = qi0 + 8;
        const bool full = (k0 + 63 <= q0 + r0);
        float mx0 = -1e30f, mx1 = -1e30f;
#pragma unroll
        for (int nt = 0; nt < 8; nt++) {
            int c = k0 + nt * 8 + 2 * t;
            float s00 = sacc[nt][0] * scale, s01 = sacc[nt][1] * scale;
            float s10 = sacc[nt][2] * scale, s11 = sacc[nt][3] * scale;
            if (!full) {
                if (c > qi0)     s00 = -1e30f;
                if (c + 1 > qi0) s01 = -1e30f;
                if (c > qi1)     s10 = -1e30f;
                if (c + 1 > qi1) s11 = -1e30f;
            }
            sacc[nt][0] = s00; sacc[nt][1] = s01;
            sacc[nt][2] = s10; sacc[nt][3] = s11;
            mx0 = fmaxf(mx0, fmaxf(s00, s01));
            mx1 = fmaxf(mx1, fmaxf(s10, s11));
        }
        mx0 = fmaxf(mx0, __shfl_xor_sync(0xffffffffu, mx0, 1));
        mx0 = fmaxf(mx0, __shfl_xor_sync(0xffffffffu, mx0, 2));
        mx1 = fmaxf(mx1, __shfl_xor_sync(0xffffffffu, mx1, 1));
        mx1 = fmaxf(mx1, __shfl_xor_sync(0xffffffffu, mx1, 2));

        float mn0 = fmaxf(m0, mx0), mn1 = fmaxf(m1, mx1);
        float a0 = __expf(m0 - mn0), a1 = __expf(m1 - mn1);
        float s0 = 0.f, s1 = 0.f;
#pragma unroll
        for (int nt = 0; nt < 8; nt++) {
            float p00 = __expf(sacc[nt][0] - mn0);
            float p01 = __expf(sacc[nt][1] - mn0);
            float p10 = __expf(sacc[nt][2] - mn1);
            float p11 = __expf(sacc[nt][3] - mn1);
            sacc[nt][0] = p00; sacc[nt][1] = p01;
            sacc[nt][2] = p10; sacc[nt][3] = p11;
            s0 += p00 + p01;
            s1 += p10 + p11;
        }
        s0 += __shfl_xor_sync(0xffffffffu, s0, 1);
        s0 += __shfl_xor_sync(0xffffffffu, s0, 2);
        s1 += __shfl_xor_sync(0xffffffffu, s1, 1);
        s1 += __shfl_xor_sync(0xffffffffu, s1, 2);
        l0 = l0 * a0 + s0;
        l1 = l1 * a1 + s1;
        m0 = mn0; m1 = mn1;
#pragma unroll
        for (int nv = 0; nv < 16; nv++) {
            oacc[nv][0] *= a0; oacc[nv][1] *= a0;
            oacc[nv][2] *= a1; oacc[nv][3] *= a1;
        }

        // wait V(cur): outstanding = {V(cur), K(next)?}
        if (pre) { CP_WAIT1; } else { CP_WAIT0; }
        __syncthreads();               // V visible to all

        // O += P @ V  (P hi/lo, V single)
        const int lrv = (lane & 7) + 8 * ((lane >> 3) & 1);
#pragma unroll
        for (int u = 0; u < 4; u++) {
            unsigned pah[4], pal[4];
            packsplit(sacc[2 * u][0],     sacc[2 * u][1],     pah[0], pal[0]);
            packsplit(sacc[2 * u][2],     sacc[2 * u][3],     pah[1], pal[1]);
            packsplit(sacc[2 * u + 1][0], sacc[2 * u + 1][1], pah[2], pal[2]);
            packsplit(sacc[2 * u + 1][2], sacc[2 * u + 1][3], pah[3], pal[3]);
            int rV = u * 16 + lrv;
#pragma unroll
            for (int nvp = 0; nvp < 8; nvp++) {
                int nv0 = 2 * nvp;
                uint32_t a = sb + OVO + rV * 256 +
                             (((nv0 + (lane >> 4)) ^ (rV & 7)) << 4);
                unsigned bv4[4];
                ldsm4t(a, bv4);
                mma_f16(oacc[nv0],     pah, &bv4[0]);
                mma_f16(oacc[nv0],     pal, &bv4[0]);
                mma_f16(oacc[nv0 + 1], pah, &bv4[2]);
                mma_f16(oacc[nv0 + 1], pal, &bv4[2]);
            }
        }

        if (pre) {
            __syncthreads();           // all warps done reading V(cur)
            load_V(k0 + 64);           // overlaps next S-phase
        }
    }

    // epilogue: normalize + hi/lo split (A side of out-proj)
    float i0 = 1.f / l0, i1 = 1.f / l1;
    int row0 = q0 + r0 + g;
#pragma unroll
    for (int nv = 0; nv < 16; nv++) {
        int col = h * DVV + nv * 8 + 2 * t;
        unsigned hw, lw;
        packsplit(oacc[nv][0] * i0, oacc[nv][1] * i0, hw, lw);
        *(unsigned*)(Oh + (size_t)row0 * (HH * DVV) + col) = hw;
        *(unsigned*)(Ol + (size_t)row0 * (HH * DVV) + col) = lw;
        packsplit(oacc[nv][2] * i1, oacc[nv][3] * i1, hw, lw);
        *(unsigned*)(Oh + (size_t)(row0 + 8) * (HH * DVV) + col) = hw;
        *(unsigned*)(Ol + (size_t)(row0 + 8) * (HH * DVV) + col) = lw;
    }
}

// ======================= launch =======================
extern "C" void kernel_launch(void* const* d_in, const int* in_sizes, int n_in,
                              void* d_out, int out_size) {
    const float* x       = (const float*)d_in[0];
    const float* w_q_a   = (const float*)d_in[1];
    const float* q_a_ln  = (const float*)d_in[2];
    const float* w_q_b   = (const float*)d_in[3];
    const float* w_kv_a  = (const float*)d_in[4];
    const float* kv_a_ln = (const float*)d_in[5];
    const float* w_kv_b  = (const float*)d_in[6];
    const float* w_out   = (const float*)d_in[7];
    float* out = (float*)d_out;

    float *c1, *qbuf;
    __half *Ah, *Al, *B1, *B2, *B3, *BO, *A2h, *A2l, *kv, *kpe;
    cudaGetSymbolAddress((void**)&c1,   g_c1);
    cudaGetSymbolAddress((void**)&qbuf, g_q);
    cudaGetSymbolAddress((void**)&Ah,   g_Ah);
    cudaGetSymbolAddress((void**)&Al,   g_Al);
    cudaGetSymbolAddress((void**)&B1,   g_B1);
    cudaGetSymbolAddress((void**)&B2,   g_B2);
    cudaGetSymbolAddress((void**)&B3,   g_B3);
    cudaGetSymbolAddress((void**)&BO,   g_BO);
    cudaGetSymbolAddress((void**)&A2h,  g_A2h);
    cudaGetSymbolAddress((void**)&A2l,  g_A2l);
    cudaGetSymbolAddress((void**)&kv,   g_kv);
    cudaGetSymbolAddress((void**)&kpe,  g_kpe);

    cudaFuncSetAttribute(bgemm2, cudaFuncAttributeMaxDynamicSharedMemorySize, BG_SMEM);
    cudaFuncSetAttribute(flash2, cudaFuncAttributeMaxDynamicSharedMemorySize, FL2_SMEM);

    cudaStream_t s2;
    cudaStreamCreateWithFlags(&s2, cudaStreamNonBlocking);
    cudaEvent_t eF0, eJ0, eG1, eF1, eJ1;
    cudaEventCreateWithFlags(&eF0, cudaEventDisableTiming);
    cudaEventCreateWithFlags(&eJ0, cudaEventDisableTiming);
    cudaEventCreateWithFlags(&eG1, cudaEventDisableTiming);
    cudaEventCreateWithFlags(&eF1, cudaEventDisableTiming);
    cudaEventCreateWithFlags(&eJ1, cudaEventDisableTiming);

    dim3 blk(256);

    // ---- main: x split; fork ALL standalone weight convs to s2 ----
    conv_split<<<(SQ * EE / 8 + 255) / 256, blk>>>(x, Ah, Al, SQ * EE);
    cudaEventRecord(eF0, 0);
    cudaStreamWaitEvent(s2, eF0, 0);
    conv_single<<<(QLR * HH * DQQ / 8 + 255) / 256, blk, 0, s2>>>(w_q_b, B3, QLR * HH * DQQ);
    conv_single<<<(KLR * HH * 256 / 8 + 255) / 256, blk, 0, s2>>>(w_kv_b, B2, KLR * HH * 256);
    conv_single<<<(HH * DVV * EE / 8 + 255) / 256, blk, 0, s2>>>(w_out, BO, HH * DVV * EE);
    cudaEventRecord(eJ0, s2);

    // ---- main: gemm1 weights + gemm1 ----
    conv_singleN<<<(EE * QLR / 8 + 255) / 256, blk>>>(w_q_a, B1, QLR, 0, N1C, EE * QLR);
    conv_singleN<<<(EE * (KLR + DRR) / 8 + 255) / 256, blk>>>(
        w_kv_a, B1, KLR + DRR, QLR, N1C, EE * (KLR + DRR));
    bgemm2<<<dim3(N1C / 128, SQ / 128), blk, BG_SMEM>>>(
        Ah, Al, B1, c1, nullptr, N1C, EE, 0);
    cudaEventRecord(eG1, 0);

    // s2: rope_k concurrent with main's rmsnorms
    cudaStreamWaitEvent(s2, eG1, 0);
    rope_k_split<<<(SQ * 32 + 255) / 256, blk, 0, s2>>>(c1 + QLR + KLR, N1C, kpe);

    // main: merged rmsnorm (qa -> Ah/Al, ckv -> A2h/A2l)
    rmsnorm2<<<dim3(SQ, 2), blk>>>(c1, q_a_ln, kv_a_ln, Ah, Al, A2h, A2l);

    // join weight convs; fork kv gemm to s2 (after rope_k on s2)
    cudaStreamWaitEvent(0, eJ0, 0);
    cudaEventRecord(eF1, 0);
    cudaStreamWaitEvent(s2, eF1, 0);
    bgemm2<<<dim3((HH * 256) / 128, SQ / 128), blk, BG_SMEM, s2>>>(
        A2h, A2l, B2, nullptr, kv, HH * 256, KLR, 1);
    cudaEventRecord(eJ1, s2);

    // main: q = qa_n @ w_q_b (concurrent with kv gemm)
    bgemm2<<<dim3((HH * DQQ) / 128, SQ / 128), blk, BG_SMEM>>>(
        Ah, Al, B3, qbuf, nullptr, HH * DQQ, QLR, 0);

    // join kv gemm (covers rope_k), attention
    cudaStreamWaitEvent(0, eJ1, 0);
    flash2<<<dim3(SQ / 64, HH), dim3(128), FL2_SMEM>>>(qbuf, kv, kpe, Ah, Al);

    // out = o @ w_out
    bgemm2<<<dim3(EE / 128, SQ / 128), blk, BG_SMEM>>>(
        Ah, Al, BO, out, nullptr, EE, HH * DVV, 0);
}

// round 17
// speedup vs baseline: 1.0164x; 1.0164x over previous
#include <cuda_runtime.h>
#include <cuda_fp16.h>
#include <math.h>
#include <stdint.h>

#define SQ   2048
#define EE   2048
#define HH   16
#define QLR  1536
#define KLR  512
#define DNN  128
#define DRR  64
#define DVV  128
#define DQQ  192
#define N1C  2176

// -------- scratch --------
__device__ float g_c1  [SQ * N1C];
__device__ float g_q   [SQ * HH * DQQ];

__device__ __half g_Ah [SQ * EE];
__device__ __half g_Al [SQ * EE];
__device__ __half g_B1 [QLR * 3072];
__device__ __half g_B3 [QLR * 3072];
__device__ __half g_B2 [KLR * HH * 256];
__device__ __half g_BO [HH * DVV * EE];
__device__ __half g_A2h[SQ * KLR];
__device__ __half g_A2l[SQ * KLR];
__device__ __half g_kv [SQ * HH * 256];
__device__ __half g_kpe[SQ * DRR];

// ======================= helpers =======================
__device__ __forceinline__ uint32_t s2u(const void* p) {
    return (uint32_t)__cvta_generic_to_shared(p);
}
__device__ __forceinline__ void cpa(uint32_t d, const void* s) {
    asm volatile("cp.async.cg.shared.global [%0], [%1], 16;\n" :: "r"(d), "l"(s));
}
#define CP_COMMIT asm volatile("cp.async.commit_group;\n")
#define CP_WAIT0  asm volatile("cp.async.wait_group 0;\n")
#define CP_WAIT1  asm volatile("cp.async.wait_group 1;\n")
#define CP_WAIT2  asm volatile("cp.async.wait_group 2;\n")

__device__ __forceinline__ void ldsm4(uint32_t a, unsigned* d) {
    asm volatile("ldmatrix.sync.aligned.m8n8.x4.shared.b16 {%0,%1,%2,%3}, [%4];\n"
        : "=r"(d[0]), "=r"(d[1]), "=r"(d[2]), "=r"(d[3]) : "r"(a));
}
__device__ __forceinline__ void ldsm4t(uint32_t a, unsigned* d) {
    asm volatile("ldmatrix.sync.aligned.m8n8.x4.trans.shared.b16 {%0,%1,%2,%3}, [%4];\n"
        : "=r"(d[0]), "=r"(d[1]), "=r"(d[2]), "=r"(d[3]) : "r"(a));
}
__device__ __forceinline__ void mma_f16(float* d, const unsigned* a, const unsigned* b) {
    asm volatile(
        "mma.sync.aligned.m16n8k16.row.col.f32.f16.f16.f32 "
        "{%0,%1,%2,%3}, {%4,%5,%6,%7}, {%8,%9}, {%0,%1,%2,%3};\n"
        : "+f"(d[0]), "+f"(d[1]), "+f"(d[2]), "+f"(d[3])
        : "r"(a[0]), "r"(a[1]), "r"(a[2]), "r"(a[3]), "r"(b[0]), "r"(b[1]));
}
__device__ __forceinline__ unsigned short hfu(__half v) {
    return *(unsigned short*)&v;
}
__device__ __forceinline__ void packsplit(float x, float y, unsigned& h, unsigned& l) {
    __half xh = __float2half(x), yh = __float2half(y);
    __half xl = __float2half(x - __half2float(xh));
    __half yl = __float2half(y - __half2float(yh));
    h = (unsigned)hfu(xh) | ((unsigned)hfu(yh) << 16);
    l = (unsigned)hfu(xl) | ((unsigned)hfu(yl) << 16);
}
__device__ __forceinline__ unsigned packh2(float x, float y) {
    __half xh = __float2half(x), yh = __float2half(y);
    return (unsigned)hfu(xh) | ((unsigned)hfu(yh) << 16);
}
__device__ __forceinline__ void split8(const float* f, uint4& hv, uint4& lv) {
    unsigned hw[4], lw[4];
#pragma unroll
    for (int j = 0; j < 4; j++) packsplit(f[2 * j], f[2 * j + 1], hw[j], lw[j]);
    hv = make_uint4(hw[0], hw[1], hw[2], hw[3]);
    lv = make_uint4(lw[0], lw[1], lw[2], lw[3]);
}

// ======================= conversions ===========================
__global__ void conv_split(const float* __restrict__ in,
                           __half* __restrict__ hi,
                           __half* __restrict__ lo, int n) {
    int i = (blockIdx.x * blockDim.x + threadIdx.x) * 8;
    if (i >= n) return;
    float f[8];
    *(float4*)&f[0] = *(const float4*)(in + i);
    *(float4*)&f[4] = *(const float4*)(in + i + 4);
    uint4 hv, lv;
    split8(f, hv, lv);
    *(uint4*)(hi + i) = hv;
    *(uint4*)(lo + i) = lv;
}
__global__ void conv_single(const float* __restrict__ in,
                            __half* __restrict__ o, int n) {
    int i = (blockIdx.x * blockDim.x + threadIdx.x) * 8;
    if (i >= n) return;
    float f[8];
    *(float4*)&f[0] = *(const float4*)(in + i);
    *(float4*)&f[4] = *(const float4*)(in + i + 4);
    unsigned w[4];
#pragma unroll
    for (int j = 0; j < 4; j++) w[j] = packh2(f[2 * j], f[2 * j + 1]);
    *(uint4*)(o + i) = make_uint4(w[0], w[1], w[2], w[3]);
}
__global__ void conv_singleN(const float* __restrict__ in,
                             __half* __restrict__ o,
                             int Nin, int colOff, int Nstr, int n) {
    int i = (blockIdx.x * blockDim.x + threadIdx.x) * 8;
    if (i >= n) return;
    int r = i / Nin, c = i % Nin;
    float f[8];
    *(float4*)&f[0] = *(const float4*)(in + i);
    *(float4*)&f[4] = *(const float4*)(in + i + 4);
    unsigned w[4];
#pragma unroll
    for (int j = 0; j < 4; j++) w[j] = packh2(f[2 * j], f[2 * j + 1]);
    *(uint4*)(o + (size_t)r * Nstr + colOff + c) = make_uint4(w[0], w[1], w[2], w[3]);
}

// ======================= merged RMSNorm (qa + ckv) ==========================
__global__ void rmsnorm2(const float* __restrict__ c1,
                         const float* __restrict__ wq,
                         const float* __restrict__ wk,
                         __half* __restrict__ qh, __half* __restrict__ ql,
                         __half* __restrict__ kh, __half* __restrict__ kl) {
    const int row = blockIdx.x;
    const int which = blockIdx.y;
    const int D = which ? KLR : QLR;
    const float* x = c1 + (size_t)row * N1C + (which ? QLR : 0);
    const float* w = which ? wk : wq;
    __half* hi = which ? kh : qh;
    __half* lo = which ? kl : ql;

    float ss = 0.f;
    for (int i = threadIdx.x; i < D; i += blockDim.x) { float v = x[i]; ss += v * v; }
#pragma unroll
    for (int m = 16; m; m >>= 1) ss += __shfl_xor_sync(0xffffffffu, ss, m);
    __shared__ float wsum[8];
    if ((threadIdx.x & 31) == 0) wsum[threadIdx.x >> 5] = ss;
    __syncthreads();
    float tot = 0.f;
#pragma unroll
    for (int i = 0; i < 8; i++) tot += wsum[i];
    float scale = rsqrtf(tot / (float)D + 1e-6f);
    for (int i = threadIdx.x; i < D; i += blockDim.x) {
        float v = x[i] * scale * w[i];
        __half h = __float2half(v);
        hi[(size_t)row * D + i] = h;
        lo[(size_t)row * D + i] = __float2half(v - __half2float(h));
    }
}

// ======================= bgemm2: fp16 A-x2 / B-x1 ===========================
#define BG_STAGE 24576
#define BG_SMEM  (3 * BG_STAGE)

__global__ __launch_bounds__(256, 2) void bgemm2(const __half* __restrict__ Ahg,
                                                 const __half* __restrict__ Alg,
                                                 const __half* __restrict__ Bg,
                                                 float* __restrict__ C,
                                                 __half* __restrict__ Ch,
                                                 int N, int K, int mode) {
    extern __shared__ char smem[];
    const uint32_t sb = s2u(smem);
    const int tid = threadIdx.x;
    const int lane = tid & 31, warp = tid >> 5;
    const int wm = warp >> 2, wn = warp & 3;
    const int g = lane >> 2, t = lane & 3;
    const int bm = blockIdx.y * 128, bn = blockIdx.x * 128;

    float acc[4][4][4];
#pragma unroll
    for (int mt = 0; mt < 4; mt++)
#pragma unroll
        for (int nt = 0; nt < 4; nt++)
#pragma unroll
            for (int k = 0; k < 4; k++) acc[mt][nt][k] = 0.f;

    const int nsteps = K >> 5;

    auto load_stage = [&](int s) {
        uint32_t base = sb + (s % 3) * BG_STAGE;
        int k0 = s << 5;
#pragma unroll
        for (int p = 0; p < 2; p++) {
            int id = tid + p * 256;
            int r = id >> 2, sg = id & 3;
            uint32_t dst = base + r * 64 + (((sg ^ ((r >> 1) & 3))) << 4);
            size_t go = (size_t)(bm + r) * K + k0 + sg * 8;
            cpa(dst, Ahg + go);
            cpa(dst + 8192, Alg + go);
        }
#pragma unroll
        for (int p = 0; p < 2; p++) {
            int id = tid + p * 256;
            int r = id >> 4, sg = id & 15;
            uint32_t dst = base + 16384 + r * 256 + ((sg ^ (r & 7)) << 4);
            size_t go = (size_t)(k0 + r) * N + bn + sg * 8;
            cpa(dst, Bg + go);
        }
        CP_COMMIT;
    };

    load_stage(0);
    if (nsteps > 1) load_stage(1);

    for (int s = 0; s < nsteps; s++) {
        if (s + 1 < nsteps) { CP_WAIT1; } else { CP_WAIT0; }
        __syncthreads();
        if (s + 2 < nsteps) load_stage(s + 2);

        uint32_t ab = sb + (s % 3) * BG_STAGE;
        uint32_t bb = ab + 16384;
        const int lr = (lane & 7) + 8 * ((lane >> 3) & 1);

#pragma unroll
        for (int kk = 0; kk < 32; kk += 16) {
            unsigned ah[4][4], al[4][4], bf[4][2];
            int sgA = (kk >> 3) + (lane >> 4);
#pragma unroll
            for (int mt = 0; mt < 4; mt++) {
                int row = wm * 64 + mt * 16 + lr;
                uint32_t a = ab + row * 64 + ((sgA ^ ((row >> 1) & 3)) << 4);
                ldsm4(a, ah[mt]);
                ldsm4(a + 8192, al[mt]);
            }
            int rB = kk + lr;
#pragma unroll
            for (int ntp = 0; ntp < 2; ntp++) {
                int sgB = wn * 4 + 2 * ntp + (lane >> 4);
                uint32_t b = bb + rB * 256 + ((sgB ^ (rB & 7)) << 4);
                unsigned t4[4];
                ldsm4t(b, t4);
                bf[2 * ntp][0] = t4[0]; bf[2 * ntp][1] = t4[1];
                bf[2 * ntp + 1][0] = t4[2]; bf[2 * ntp + 1][1] = t4[3];
            }
#pragma unroll
            for (int mt = 0; mt < 4; mt++)
#pragma unroll
                for (int nt = 0; nt < 4; nt++) {
                    mma_f16(acc[mt][nt], ah[mt], bf[nt]);
                    mma_f16(acc[mt][nt], al[mt], bf[nt]);
                }
        }
    }

    if (mode == 0) {
#pragma unroll
        for (int mt = 0; mt < 4; mt++) {
            int row = bm + wm * 64 + mt * 16 + g;
#pragma unroll
            for (int nt = 0; nt < 4; nt++) {
                int col = bn + wn * 32 + nt * 8 + 2 * t;
                if (col < N) {
                    *(float2*)&C[(size_t)row * N + col] =
                        make_float2(acc[mt][nt][0], acc[mt][nt][1]);
                    *(float2*)&C[(size_t)(row + 8) * N + col] =
                        make_float2(acc[mt][nt][2], acc[mt][nt][3]);
                }
            }
        }
    } else {
#pragma unroll
        for (int mt = 0; mt < 4; mt++) {
            int row = bm + wm * 64 + mt * 16 + g;
#pragma unroll
            for (int nt = 0; nt < 4; nt++) {
                int col = bn + wn * 32 + nt * 8 + 2 * t;
                *(unsigned*)(Ch + (size_t)row * N + col) =
                    packh2(acc[mt][nt][0], acc[mt][nt][1]);
                *(unsigned*)(Ch + (size_t)(row + 8) * N + col) =
                    packh2(acc[mt][nt][2], acc[mt][nt][3]);
            }
        }
    }
}

// ======================= RoPE-K =============================================
#define LOG2_10000_OVER_32 0.4152410118609203f

__global__ void rope_k_split(const float* __restrict__ src, int stride,
                             __half* __restrict__ kpe) {
    int w = (blockIdx.x * blockDim.x + threadIdx.x) >> 5;
    int lane = threadIdx.x & 31;
    if (w >= SQ) return;
    const float* base = src + (size_t)w * stride;
    float x0 = base[2 * lane];
    float x1 = base[2 * lane + 1];
    float invf = exp2f(-(float)lane * LOG2_10000_OVER_32);
    float ang = (float)w * invf;
    float sn, cs;
    sincosf(ang, &sn, &cs);
    kpe[(size_t)w * DRR + lane]      = __float2half(x0 * cs - x1 * sn);
    kpe[(size_t)w * DRR + 32 + lane] = __float2half(x1 * cs + x0 * sn);
}

// ======================= flash2: BM=64, occ 2 (R15 loop) ====================
// smem: Qh 0..24K, Ql 24K..48K, K 48K..72K, V 72K..88K.
#define OQH 0
#define OQL 24576
#define OKO 49152
#define OVO 73728
#define FL2_SMEM 90112

__global__ __launch_bounds__(128) void flash2(const float* __restrict__ q,
                                              const __half* __restrict__ kv,
                                              const __half* __restrict__ kpe,
                                              __half* __restrict__ Oh,
                                              __half* __restrict__ Ol) {
    extern __shared__ char smem[];
    const uint32_t sb = s2u(smem);
    const int tid = threadIdx.x, lane = tid & 31, warp = tid >> 5;
    const int g = lane >> 2, t = lane & 3;
    const int h = blockIdx.y;
    const int qb = gridDim.x - 1 - blockIdx.x;   // LPT: longest first
    const int q0 = qb * 64;
    const int r0 = warp * 16;
    const float scale = 0.07216878364870322f;

    auto load_KV = [&](int k0) {
        for (int i = tid; i < 64 * 24; i += 128) {
            int r = i / 24, sg = i % 24;
            uint32_t off = r * 384 + ((sg ^ (r & 7)) << 4);
            if (sg < 16) {
                cpa(sb + OKO + off, kv + (size_t)(k0 + r) * (HH * 256) + h * 256 + sg * 8);
            } else {
                cpa(sb + OKO + off, kpe + (size_t)(k0 + r) * DRR + (sg - 16) * 8);
            }
        }
        for (int i = tid; i < 64 * 16; i += 128) {
            int r = i / 16, sg = i % 16;
            uint32_t off = r * 256 + ((sg ^ (r & 7)) << 4);
            cpa(sb + OVO + off, kv + (size_t)(k0 + r) * (HH * 256) + h * 256 + DNN + sg * 8);
        }
        CP_COMMIT;
    };

    // kick off first K/V load, then do Q while it flies
    load_KV(0);

    // ---- Q load with fused RoPE + hi/lo split ----
    for (int i = tid; i < 64 * 24; i += 128) {
        int r = i / 24, sg = i % 24;
        int qrow = q0 + r;
        const float* qr = q + (size_t)qrow * (HH * DQQ) + h * DQQ;
        float f[8];
        if (sg < 16) {
            *(float4*)&f[0] = *(const float4*)(qr + sg * 8);
            *(float4*)&f[4] = *(const float4*)(qr + sg * 8 + 4);
        } else {
            int u_base = (sg - 16) * 8;
            int j_base = u_base & 31;
            float f2[16];
            const float* pe = qr + DNN + 2 * j_base;
#pragma unroll
            for (int v = 0; v < 4; v++) *(float4*)&f2[4 * v] = *(const float4*)(pe + 4 * v);
#pragma unroll
            for (int j2 = 0; j2 < 8; j2++) {
                int j = j_base + j2;
                float x0 = f2[2 * j2], x1 = f2[2 * j2 + 1];
                float invf = exp2f(-(float)j * LOG2_10000_OVER_32);
                float sn, cs;
                sincosf((float)qrow * invf, &sn, &cs);
                f[j2] = (u_base < 32) ? (x0 * cs - x1 * sn) : (x1 * cs + x0 * sn);
            }
        }
        uint4 hv, lv;
        split8(f, hv, lv);
        uint32_t off = r * 384 + ((sg ^ (r & 7)) << 4);
        *(uint4*)(smem + OQH + off) = hv;
        *(uint4*)(smem + OQL + off) = lv;
    }

    float m0 = -1e30f, m1 = -1e30f, l0 = 0.f, l1 = 0.f;
    float oacc[16][4];
#pragma unroll
    for (int nv = 0; nv < 16; nv++)
#pragma unroll
        for (int k = 0; k < 4; k++) oacc[nv][k] = 0.f;

    const int nkb = qb + 1;
    for (int kb = 0; kb < nkb; kb++) {
        const int k0 = kb * 64;
        CP_WAIT0;
        __syncthreads();

        // S = Q @ K^T
        float sacc[8][4];
#pragma unroll
        for (int nt = 0; nt < 8; nt++)
#pragma unroll
            for (int k = 0; k < 4; k++) sacc[nt][k] = 0.f;

        const int lr = (lane & 7) + 8 * ((lane >> 3) & 1);
#pragma unroll
        for (int kk = 0; kk < 192; kk += 16) {
            unsigned ah[4], al[4];
            int rowA = r0 + lr;
            int sgA = (kk >> 3) + (lane >> 4);
            uint32_t a = sb + OQH + rowA * 384 + ((sgA ^ (rowA & 7)) << 4);
            ldsm4(a, ah);
            ldsm4(a + (OQL - OQH), al);
            int sgB = (kk >> 3) + ((lane >> 3) & 1);
#pragma unroll
            for (int ntp = 0; ntp < 4; ntp++) {
                int rB = (2 * ntp + (lane >> 4)) * 8 + (lane & 7);
                uint32_t b = sb + OKO + rB * 384 + ((sgB ^ (rB & 7)) << 4);
                unsigned b4[4];
                ldsm4(b, b4);
                mma_f16(sacc[2 * ntp],     ah, &b4[0]);
                mma_f16(sacc[2 * ntp],     al, &b4[0]);
                mma_f16(sacc[2 * ntp + 1], ah, &b4[2]);
                mma_f16(sacc[2 * ntp + 1], al, &b4[2]);
            }
        }

        // mask + online softmax
        const int qi0 = q0 + r0 + g;
        const int qi1 = qi0 + 8;
        const bool full = (k0 + 63 <= q0 + r0);
        float mx0 = -1e30f, mx1 = -1e30f;
#pragma unroll
        for (int nt = 0; nt < 8; nt++) {
            int c = k0 + nt * 8 + 2 * t;
            float s00 = sacc[nt][0] * scale, s01 = sacc[nt][1] * scale;
            float s10 = sacc[nt][2] * scale, s11 = sacc[nt][3] * scale;
            if (!full) {
                if (c > qi0)     s00 = -1e30f;
                if (c + 1 > qi0) s01 = -1e30f;
                if (c > qi1)     s10 = -1e30f;
                if (c + 1 > qi1) s11 = -1e30f;
            }
            sacc[nt][0] = s00; sacc[nt][1] = s01;
            sacc[nt][2] = s10; sacc[nt][3] = s11;
            mx0 = fmaxf(mx0, fmaxf(s00, s01));
            mx1 = fmaxf(mx1, fmaxf(s10, s11));
        }
        mx0 = fmaxf(mx0, __shfl_xor_sync(0xffffffffu, mx0, 1));
        mx0 = fmaxf(mx0, __shfl_xor_sync(0xffffffffu, mx0, 2));
        mx1 = fmaxf(mx1, __shfl_xor_sync(0xffffffffu, mx1, 1));
        mx1 = fmaxf(mx1, __shfl_xor_sync(0xffffffffu, mx1, 2));

        float mn0 = fmaxf(m0, mx0), mn1 = fmaxf(m1, mx1);
        float a0 = __expf(m0 - mn0), a1 = __expf(m1 - mn1);
        float s0 = 0.f, s1 = 0.f;
#pragma unroll
        for (int nt = 0; nt < 8; nt++) {
            float p00 = __expf(sacc[nt][0] - mn0);
            float p01 = __expf(sacc[nt][1] - mn0);
            float p10 = __expf(sacc[nt][2] - mn1);
            float p11 = __expf(sacc[nt][3] - mn1);
            sacc[nt][0] = p00; sacc[nt][1] = p01;
            sacc[nt][2] = p10; sacc[nt][3] = p11;
            s0 += p00 + p01;
            s1 += p10 + p11;
        }
        s0 += __shfl_xor_sync(0xffffffffu, s0, 1);
        s0 += __shfl_xor_sync(0xffffffffu, s0, 2);
        s1 += __shfl_xor_sync(0xffffffffu, s1, 1);
        s1 += __shfl_xor_sync(0xffffffffu, s1, 2);
        l0 = l0 * a0 + s0;
        l1 = l1 * a1 + s1;
        m0 = mn0; m1 = mn1;
#pragma unroll
        for (int nv = 0; nv < 16; nv++) {
            oacc[nv][0] *= a0; oacc[nv][1] *= a0;
            oacc[nv][2] *= a1; oacc[nv][3] *= a1;
        }

        // O += P @ V  (P hi/lo, V single)
        const int lrv = (lane & 7) + 8 * ((lane >> 3) & 1);
#pragma unroll
        for (int u = 0; u < 4; u++) {
            unsigned pah[4], pal[4];
            packsplit(sacc[2 * u][0],     sacc[2 * u][1],     pah[0], pal[0]);
            packsplit(sacc[2 * u][2],     sacc[2 * u][3],     pah[1], pal[1]);
            packsplit(sacc[2 * u + 1][0], sacc[2 * u + 1][1], pah[2], pal[2]);
            packsplit(sacc[2 * u + 1][2], sacc[2 * u + 1][3], pah[3], pal[3]);
            int rV = u * 16 + lrv;
#pragma unroll
            for (int nvp = 0; nvp < 8; nvp++) {
                int nv0 = 2 * nvp;
                uint32_t a = sb + OVO + rV * 256 +
                             (((nv0 + (lane >> 4)) ^ (rV & 7)) << 4);
                unsigned bv4[4];
                ldsm4t(a, bv4);
                mma_f16(oacc[nv0],     pah, &bv4[0]);
                mma_f16(oacc[nv0],     pal, &bv4[0]);
                mma_f16(oacc[nv0 + 1], pah, &bv4[2]);
                mma_f16(oacc[nv0 + 1], pal, &bv4[2]);
            }
        }

        // launch next K/V load (buffers free: all reads this iter done)
        if (kb + 1 < nkb) {
            __syncthreads();
            load_KV(k0 + 64);
        }
    }

    // epilogue: normalize + hi/lo split (A side of out-proj)
    float i0 = 1.f / l0, i1 = 1.f / l1;
    int row0 = q0 + r0 + g;
#pragma unroll
    for (int nv = 0; nv < 16; nv++) {
        int col = h * DVV + nv * 8 + 2 * t;
        unsigned hw, lw;
        packsplit(oacc[nv][0] * i0, oacc[nv][1] * i0, hw, lw);
        *(unsigned*)(Oh + (size_t)row0 * (HH * DVV) + col) = hw;
        *(unsigned*)(Ol + (size_t)row0 * (HH * DVV) + col) = lw;
        packsplit(oacc[nv][2] * i1, oacc[nv][3] * i1, hw, lw);
        *(unsigned*)(Oh + (size_t)(row0 + 8) * (HH * DVV) + col) = hw;
        *(unsigned*)(Ol + (size_t)(row0 + 8) * (HH * DVV) + col) = lw;
    }
}

// ======================= launch =======================
extern "C" void kernel_launch(void* const* d_in, const int* in_sizes, int n_in,
                              void* d_out, int out_size) {
    const float* x       = (const float*)d_in[0];
    const float* w_q_a   = (const float*)d_in[1];
    const float* q_a_ln  = (const float*)d_in[2];
    const float* w_q_b   = (const float*)d_in[3];
    const float* w_kv_a  = (const float*)d_in[4];
    const float* kv_a_ln = (const float*)d_in[5];
    const float* w_kv_b  = (const float*)d_in[6];
    const float* w_out   = (const float*)d_in[7];
    float* out = (float*)d_out;

    float *c1, *qbuf;
    __half *Ah, *Al, *B1, *B2, *B3, *BO, *A2h, *A2l, *kv, *kpe;
    cudaGetSymbolAddress((void**)&c1,   g_c1);
    cudaGetSymbolAddress((void**)&qbuf, g_q);
    cudaGetSymbolAddress((void**)&Ah,   g_Ah);
    cudaGetSymbolAddress((void**)&Al,   g_Al);
    cudaGetSymbolAddress((void**)&B1,   g_B1);
    cudaGetSymbolAddress((void**)&B2,   g_B2);
    cudaGetSymbolAddress((void**)&B3,   g_B3);
    cudaGetSymbolAddress((void**)&BO,   g_BO);
    cudaGetSymbolAddress((void**)&A2h,  g_A2h);
    cudaGetSymbolAddress((void**)&A2l,  g_A2l);
    cudaGetSymbolAddress((void**)&kv,   g_kv);
    cudaGetSymbolAddress((void**)&kpe,  g_kpe);

    cudaFuncSetAttribute(bgemm2, cudaFuncAttributeMaxDynamicSharedMemorySize, BG_SMEM);
    cudaFuncSetAttribute(flash2, cudaFuncAttributeMaxDynamicSharedMemorySize, FL2_SMEM);

    cudaStream_t s2;
    cudaStreamCreateWithFlags(&s2, cudaStreamNonBlocking);
    cudaEvent_t eF0, eJ0, eF1, eJ1;
    cudaEventCreateWithFlags(&eF0, cudaEventDisableTiming);
    cudaEventCreateWithFlags(&eJ0, cudaEventDisableTiming);
    cudaEventCreateWithFlags(&eF1, cudaEventDisableTiming);
    cudaEventCreateWithFlags(&eJ1, cudaEventDisableTiming);

    dim3 blk(256);

    // ---- main: x split; fork ALL standalone weight convs to s2 ----
    conv_split<<<(SQ * EE / 8 + 255) / 256, blk>>>(x, Ah, Al, SQ * EE);
    cudaEventRecord(eF0, 0);
    cudaStreamWaitEvent(s2, eF0, 0);
    conv_single<<<(QLR * HH * DQQ / 8 + 255) / 256, blk, 0, s2>>>(w_q_b, B3, QLR * HH * DQQ);
    conv_single<<<(KLR * HH * 256 / 8 + 255) / 256, blk, 0, s2>>>(w_kv_b, B2, KLR * HH * 256);
    conv_single<<<(HH * DVV * EE / 8 + 255) / 256, blk, 0, s2>>>(w_out, BO, HH * DVV * EE);
    cudaEventRecord(eJ0, s2);

    // ---- main: gemm1 weights + gemm1 ----
    conv_singleN<<<(EE * QLR / 8 + 255) / 256, blk>>>(w_q_a, B1, QLR, 0, N1C, EE * QLR);
    conv_singleN<<<(EE * (KLR + DRR) / 8 + 255) / 256, blk>>>(
        w_kv_a, B1, KLR + DRR, QLR, N1C, EE * (KLR + DRR));
    bgemm2<<<dim3(N1C / 128, SQ / 128), blk, BG_SMEM>>>(
        Ah, Al, B1, c1, nullptr, N1C, EE, 0);

    // main: rope_k, then merged rmsnorm (qa -> Ah/Al, ckv -> A2h/A2l)
    rope_k_split<<<(SQ * 32 + 255) / 256, blk>>>(c1 + QLR + KLR, N1C, kpe);
    rmsnorm2<<<dim3(SQ, 2), blk>>>(c1, q_a_ln, kv_a_ln, Ah, Al, A2h, A2l);

    // join weight convs; fork kv gemm to s2
    cudaStreamWaitEvent(0, eJ0, 0);
    cudaEventRecord(eF1, 0);
    cudaStreamWaitEvent(s2, eF1, 0);
    bgemm2<<<dim3((HH * 256) / 128, SQ / 128), blk, BG_SMEM, s2>>>(
        A2h, A2l, B2, nullptr, kv, HH * 256, KLR, 1);
    cudaEventRecord(eJ1, s2);

    // main: q = qa_n @ w_q_b (concurrent with kv gemm)
    bgemm2<<<dim3((HH * DQQ) / 128, SQ / 128), blk, BG_SMEM>>>(
        Ah, Al, B3, qbuf, nullptr, HH * DQQ, QLR, 0);

    // join kv gemm, attention (BM=64, 128 threads, occ 2)
    cudaStreamWaitEvent(0, eJ1, 0);
    flash2<<<dim3(SQ / 64, HH), dim3(128), FL2_SMEM>>>(qbuf, kv, kpe, Ah, Al);

    // out = o @ w_out
    bgemm2<<<dim3(EE / 128, SQ / 128), blk, BG_SMEM>>>(
        Ah, Al, BO, out, nullptr, EE, HH * DVV, 0);
}